// round 2
// baseline (speedup 1.0000x reference)
#include <cuda_runtime.h>
#include <math.h>

// SkewSymMatrixExp: out[b] = expm(S_b), S_b = 64x64 skew-symmetric from S_vec[b].
// Scaling & squaring, s=4 (B = S/16), degree-9 Taylor via Paterson-Stockmeyer q=2:
//   P = Q0 + B2(Q1 + B2(Q2 + B2(Q3 + B2*Q4))),  Qi = a_i I + b_i B
// then 4 squarings. 9 matmuls of 64^3.
//
// All matmuls use packed fp32x2 FFMA (Blackwell f32x2) in k-major form:
//   mm(A, Bt) = A * Bt^T   (both operands k-contiguous; each FFMA2 does 2 k-steps)
// Transposed right-operands come free from skew-symmetry (B^T=-B, B2^T=B2) or from
// transposed register-tile stores of the producing matmul.

#define LDP 68              // row pitch in floats; 16*LDP % 128 == 16 -> conflict-free k-major loads
#define MATF (64 * LDP)

union F2 { unsigned long long u; float2 f; };

static __device__ __forceinline__ void ffma2(F2& d, const F2 a, const F2 b) {
    asm("fma.rn.f32x2 %0, %1, %2, %3;" : "=l"(d.u) : "l"(a.u), "l"(b.u), "l"(d.u));
}

static __device__ __forceinline__ int tri_off(int i) {
    return (i * (127 - i)) >> 1;   // strict-upper pairs before row i
}

// C = sgn * (A * Bt^T). A, Bt row-major pitch LDP in smem (k contiguous).
// Optional normal store to Cn (row pitch ldc) and/or transposed store to Ct (pitch LDP).
// 256 threads; thread (tx,ty) owns rows {ty+16i}, cols {tx+16j}, i,j in 0..3.
static __device__ __noinline__ void mm_f2(
    const float* __restrict__ A, const float* __restrict__ Bt,
    float* Cn, int ldc, float* Ct, float sgn)
{
    const int tx = threadIdx.x & 15;
    const int ty = threadIdx.x >> 4;

    F2 acc[4][4];
#pragma unroll
    for (int i = 0; i < 4; i++)
#pragma unroll
        for (int j = 0; j < 4; j++) acc[i][j].u = 0ULL;

    const float* Ab = A + ty * LDP;
    const float* Bb = Bt + tx * LDP;

#pragma unroll
    for (int kb = 0; kb < 16; kb++) {
        const int k4 = kb * 4;
        ulonglong2 av[4], bv[4];
#pragma unroll
        for (int i = 0; i < 4; i++)
            av[i] = *reinterpret_cast<const ulonglong2*>(Ab + i * (16 * LDP) + k4);
#pragma unroll
        for (int j = 0; j < 4; j++)
            bv[j] = *reinterpret_cast<const ulonglong2*>(Bb + j * (16 * LDP) + k4);
#pragma unroll
        for (int i = 0; i < 4; i++) {
            F2 a0, a1; a0.u = av[i].x; a1.u = av[i].y;
#pragma unroll
            for (int j = 0; j < 4; j++) {
                F2 b0, b1; b0.u = bv[j].x; b1.u = bv[j].y;
                ffma2(acc[i][j], a0, b0);
                ffma2(acc[i][j], a1, b1);
            }
        }
    }

    float cv[4][4];
#pragma unroll
    for (int i = 0; i < 4; i++)
#pragma unroll
        for (int j = 0; j < 4; j++)
            cv[i][j] = (acc[i][j].f.x + acc[i][j].f.y) * sgn;

    if (Cn) {
#pragma unroll
        for (int i = 0; i < 4; i++)
#pragma unroll
            for (int j = 0; j < 4; j++)
                Cn[(ty + 16 * i) * ldc + (tx + 16 * j)] = cv[i][j];
    }
    if (Ct) {
#pragma unroll
        for (int i = 0; i < 4; i++)
#pragma unroll
            for (int j = 0; j < 4; j++)
                Ct[(tx + 16 * j) * LDP + (ty + 16 * i)] = cv[i][j];
    }
}

// dst = aI*I + bB*B + cM*M (elementwise over 64x64)
static __device__ __forceinline__ void eval_lin(
    float* __restrict__ dst, const float* __restrict__ B, const float* __restrict__ M,
    float aI, float bB, float cM)
{
    const int tid = threadIdx.x;
#pragma unroll
    for (int t = 0; t < 16; t++) {
        int idx = tid + t * 256;
        int r = idx >> 6;
        int c = idx & 63;
        int off = r * LDP + c;
        float val = bB * B[off] + cM * M[off];
        if (r == c) val += aI;
        dst[off] = val;
    }
}

__global__ __launch_bounds__(256, 2)
void SkewSymMatrixExp_kernel(const float* __restrict__ Svec, float* __restrict__ out)
{
    extern __shared__ float sm[];
    float* P0 = sm;              // B
    float* P1 = P0 + MATF;       // B2 / R_R / ping-pong
    float* P2 = P1 + MATF;       // R^T chain / R_L / ping-pong
    float* P3 = P2 + MATF;       // M^T scratch / ping-pong
    float* P4 = P3 + MATF;       // M / ping-pong

    const int tid = threadIdx.x;
    const int b = blockIdx.x;
    const float* v = Svec + (size_t)b * 2016;

    // zero diagonal of B (off-diagonals fully written by scatter)
    if (tid < 64) P0[tid * LDP + tid] = 0.f;

    // scatter: B[i][j] = -v[n]/16, B[j][i] = +v[n]/16
    const float scl = 0.0625f;
    for (int n = tid; n < 2016; n += 256) {
        int i = (int)((127.0f - sqrtf(16129.0f - 8.0f * (float)n)) * 0.5f);
        if (i < 0) i = 0;
        if (i > 62) i = 62;
        while (tri_off(i + 1) <= n) ++i;
        while (tri_off(i) > n) --i;
        int j = i + 1 + (n - tri_off(i));
        float val = v[n] * scl;
        P0[i * LDP + j] = -val;
        P0[j * LDP + i] =  val;
    }
    __syncthreads();

    // Taylor coeffs a_i = 1/(2i)!, b_i = 1/(2i+1)!
    const float a1 = 0.5f,            b1 = 1.6666667e-1f;
    const float a2 = 4.1666668e-2f,   b2 = 8.3333333e-3f;
    const float a3 = 1.3888889e-3f,   b3 = 1.9841270e-4f;
    const float a4 = 2.4801587e-5f,   b4 = 2.7557319e-6f;

    // B2 = -(B * (B-as-right)) since using B as k-major right operand yields B^T = -B
    mm_f2(P0, P0, P1, LDP, nullptr, -1.0f);
    // R4^T = a4 I + b4 B^T = a4 I - b4 B
    eval_lin(P2, P0, P0, a4, -b4, 0.0f);
    __syncthreads();

    // chain i = 3, 2, 1:  M^T = (B2 * R)^T ;  R^T = a_i I - b_i B + M^T
    mm_f2(P1, P2, nullptr, 0, P3, 1.0f);
    __syncthreads();
    eval_lin(P2, P0, P3, a3, -b3, 1.0f);
    __syncthreads();

    mm_f2(P1, P2, nullptr, 0, P3, 1.0f);
    __syncthreads();
    eval_lin(P2, P0, P3, a2, -b2, 1.0f);
    __syncthreads();

    mm_f2(P1, P2, nullptr, 0, P3, 1.0f);
    __syncthreads();
    eval_lin(P2, P0, P3, a1, -b1, 1.0f);
    __syncthreads();

    // i = 0: need both M and M^T
    mm_f2(P1, P2, P4, LDP, P3, 1.0f);
    __syncthreads();
    // R_L = I + B + M   (into P2; old R^T dead),  R_R = R^T = I - B + M^T (into P1; B2 dead)
    eval_lin(P2, P0, P4, 1.0f,  1.0f, 1.0f);
    eval_lin(P1, P0, P3, 1.0f, -1.0f, 1.0f);
    __syncthreads();

    // 4 squarings: mm(L, R^T) = L*L, dual-store L and L^T for the next round
    mm_f2(P2, P1, P3, LDP, P4, 1.0f);
    __syncthreads();
    mm_f2(P3, P4, P2, LDP, P1, 1.0f);
    __syncthreads();
    mm_f2(P2, P1, P3, LDP, P4, 1.0f);
    __syncthreads();
    // final squaring straight to global (row pitch 64)
    mm_f2(P3, P4, out + (size_t)b * 4096, 64, nullptr, 1.0f);
}

extern "C" void kernel_launch(void* const* d_in, const int* in_sizes, int n_in,
                              void* d_out, int out_size)
{
    const float* svec = (const float*)d_in[0];
    float* out = (float*)d_out;
    const int batch = in_sizes[0] / 2016;

    const int smem_bytes = 5 * MATF * sizeof(float);   // 87040 B -> 2 CTAs/SM
    cudaFuncSetAttribute(SkewSymMatrixExp_kernel,
                         cudaFuncAttributeMaxDynamicSharedMemorySize, smem_bytes);
    SkewSymMatrixExp_kernel<<<batch, 256, smem_bytes>>>(svec, out);
}

// round 4
// speedup vs baseline: 1.2929x; 1.2929x over previous
#include <cuda_runtime.h>
#include <cuda_bf16.h>
#include <mma.h>
#include <math.h>
#include <stdint.h>

using namespace nvcuda;

// expm(S) for 4096 skew-symmetric 64x64 matrices.
// Scaling & squaring (s=4), degree-9 Paterson-Stockmeyer, 9 matmuls of 64^3,
// each on tensor cores via wmma bf16 (split hi/lo, fp32 accumulate, 3 products).
//
// Chain keeps A-operand fixed (= B2) for the 4 PS matmuls; all needed
// transposes come from column reads of fp32 scratch + skew-symmetry.

#define LDO 136     // operand pitch (bf16 elems) = 272 B: 16B-aligned, conflict-free ldmatrix
#define SPS 68      // scratch pitch (fp32) = 272 B
#define SBP 65      // skew-matrix pitch (fp32)

#define SM_A    0        // A operand: 64 x [hi(64)|lo(64)] bf16, pitch 136 -> 17408 B
#define SM_B    17408    // B operand (holds R^T rows), same layout     -> 17408 B
#define SM_SB   34816    // fp32 skew matrix B, pitch 65                -> 16640 B
#define SM_SCR  51456    // fp32 scratch (matmul result), pitch 68      -> 17408 B
#define SMEM_BYTES 68864

static __device__ __forceinline__ void splitw(float x0, float x1, uint32_t& hw, uint32_t& lw) {
    __nv_bfloat16 h0 = __float2bfloat16(x0), h1 = __float2bfloat16(x1);
    float r0 = x0 - __bfloat162float(h0), r1 = x1 - __bfloat162float(h1);
    __nv_bfloat16 l0 = __float2bfloat16(r0), l1 = __float2bfloat16(r1);
    hw = (uint32_t)__bfloat16_as_ushort(h0) | ((uint32_t)__bfloat16_as_ushort(h1) << 16);
    lw = (uint32_t)__bfloat16_as_ushort(l0) | ((uint32_t)__bfloat16_as_ushort(l1) << 16);
}

// A-buf row r: x_k = bB*sB[r][k] + (withScr ? scr[r][k] : 0) + aI*(k==r)
static __device__ __forceinline__ void buildA(
    __nv_bfloat16* Abuf, const float* sB, const float* scr,
    int r, float aI, float bB, bool withScr)
{
    uint32_t* hrow = reinterpret_cast<uint32_t*>(Abuf + r * LDO);
    uint32_t* lrow = hrow + 32;
    const float* srow = scr + r * SPS;
    const float* brow = sB + r * SBP;
#pragma unroll 8
    for (int k = 0; k < 64; k += 2) {
        float x0 = bB * brow[k]     + (withScr ? srow[k]     : 0.f);
        float x1 = bB * brow[k + 1] + (withScr ? srow[k + 1] : 0.f);
        if (k == r)     x0 += aI;
        if (k + 1 == r) x1 += aI;
        uint32_t hw, lw; splitw(x0, x1, hw, lw);
        hrow[k >> 1] = hw;
        lrow[k >> 1] = lw;
    }
}

// B-buf row n (holds R^T row n): x_k = bT*sB[n][k] + (withScr ? scr[k][n] : 0) + aI*(k==n)
static __device__ __forceinline__ void buildB(
    __nv_bfloat16* Bbuf, const float* sB, const float* scr,
    int n, int k0, float aI, float bT, bool withScr)
{
    uint32_t* hrow = reinterpret_cast<uint32_t*>(Bbuf + n * LDO);
    uint32_t* lrow = hrow + 32;
    const float* brow = sB + n * SBP;
#pragma unroll 8
    for (int k = k0; k < k0 + 32; k += 2) {
        float x0 = bT * brow[k]     + (withScr ? scr[k * SPS + n]       : 0.f);
        float x1 = bT * brow[k + 1] + (withScr ? scr[(k + 1) * SPS + n] : 0.f);
        if (k == n)     x0 += aI;
        if (k + 1 == n) x1 += aI;
        uint32_t hw, lw; splitw(x0, x1, hw, lw);
        hrow[k >> 1] = hw;
        lrow[k >> 1] = lw;
    }
}

// C(64x64) = A * B (split-bf16, 3 products), warp quadrant decomposition.
static __device__ __forceinline__ void mm_step(
    const __nv_bfloat16* __restrict__ Abuf, const __nv_bfloat16* __restrict__ Bbuf,
    float* dst, int ldd, int wid)
{
    const int r0 = (wid >> 1) * 32;
    const int c0 = (wid & 1) * 32;

    wmma::fragment<wmma::accumulator, 16, 16, 16, float> acc[2][2];
#pragma unroll
    for (int i = 0; i < 2; i++)
#pragma unroll
        for (int j = 0; j < 2; j++) wmma::fill_fragment(acc[i][j], 0.f);

    const int AO[3] = { 0, 64, 0 };   // Ah*Bh + Al*Bh + Ah*Bl
    const int BO[3] = { 0, 0, 64 };

#pragma unroll
    for (int p = 0; p < 3; p++) {
#pragma unroll
        for (int kt = 0; kt < 4; kt++) {
            const int ka = AO[p] + kt * 16;
            const int kb = BO[p] + kt * 16;
            wmma::fragment<wmma::matrix_a, 16, 16, 16, __nv_bfloat16, wmma::row_major> a0, a1;
            wmma::fragment<wmma::matrix_b, 16, 16, 16, __nv_bfloat16, wmma::col_major> b0, b1;
            wmma::load_matrix_sync(a0, Abuf + r0 * LDO + ka, LDO);
            wmma::load_matrix_sync(a1, Abuf + (r0 + 16) * LDO + ka, LDO);
            wmma::load_matrix_sync(b0, Bbuf + c0 * LDO + kb, LDO);
            wmma::load_matrix_sync(b1, Bbuf + (c0 + 16) * LDO + kb, LDO);
            wmma::mma_sync(acc[0][0], a0, b0, acc[0][0]);
            wmma::mma_sync(acc[0][1], a0, b1, acc[0][1]);
            wmma::mma_sync(acc[1][0], a1, b0, acc[1][0]);
            wmma::mma_sync(acc[1][1], a1, b1, acc[1][1]);
        }
    }
#pragma unroll
    for (int i = 0; i < 2; i++)
#pragma unroll
        for (int j = 0; j < 2; j++)
            wmma::store_matrix_sync(dst + (r0 + 16 * i) * ldd + c0 + 16 * j,
                                    acc[i][j], ldd, wmma::mem_row_major);
}

__global__ void __launch_bounds__(128, 3)
SkewSymMatrixExp_kernel(const float* __restrict__ Svec, float* __restrict__ out)
{
    extern __shared__ char smem[];
    __nv_bfloat16* Abuf = reinterpret_cast<__nv_bfloat16*>(smem + SM_A);
    __nv_bfloat16* Bbuf = reinterpret_cast<__nv_bfloat16*>(smem + SM_B);
    float* sB  = reinterpret_cast<float*>(smem + SM_SB);
    float* scr = reinterpret_cast<float*>(smem + SM_SCR);

    const int tid = threadIdx.x, wid = tid >> 5;
    const float* v = Svec + (size_t)blockIdx.x * 2016;

    // ---- scatter S_vec into fp32 skew matrix B = S/16 (pitch 65)
    if (tid < 64) sB[tid * SBP + tid] = 0.f;
    const float scl = 0.0625f;
    for (int n = tid; n < 2016; n += 128) {
        int i = (int)((127.0f - sqrtf(16129.0f - 8.0f * (float)n)) * 0.5f);
        if (i < 0) i = 0;
        if (i > 62) i = 62;
        while ((((i + 1) * (126 - i)) >> 1) <= n) ++i;
        while (((i * (127 - i)) >> 1) > n) --i;
        int j = i + 1 + (n - ((i * (127 - i)) >> 1));
        float val = v[n] * scl;
        sB[i * SBP + j] = -val;
        sB[j * SBP + i] = val;
    }
    __syncthreads();

    // ---- initial operands: A = B rows; B-op = B^T rows = -B rows
    if (tid < 64) buildA(Abuf, sB, scr, tid, 0.f, 1.f, false);
    else          buildB(Bbuf, sB, scr, tid - 64, 0, 0.f, -1.f, false);
    if (tid >= 64) buildB(Bbuf, sB, scr, tid - 64, 32, 0.f, -1.f, false);
    __syncthreads();

    // Taylor coeffs a_i = 1/(2i)!, b_i = 1/(2i+1)!
    const float A4 = 2.4801587e-5f, B4 = 2.7557319e-6f;
    const float A3 = 1.3888889e-3f, B3 = 1.9841270e-4f;
    const float A2 = 4.1666668e-2f, B2c = 8.3333333e-3f;
    const float A1 = 0.5f,          B1 = 1.6666667e-1f;

    // ---- step 0: B2 = B*B.  A <- B2 (fixed for chain), B-op <- r4^T = a4 I - b4 B
    mm_step(Abuf, Bbuf, scr, SPS, wid);
    __syncthreads();
    if (tid < 64) buildA(Abuf, sB, scr, tid, 0.f, 0.f, true);
    else {
        buildB(Bbuf, sB, scr, tid - 64, 0,  A4, -B4, false);
        buildB(Bbuf, sB, scr, tid - 64, 32, A4, -B4, false);
    }
    __syncthreads();

    // ---- chain: r_{i-1} = a I + b B + B2*r_i  (B-op rebuild only, A stays B2)
    const float av[3] = { A3, A2, A1 };
    const float bv[3] = { B3, B2c, B1 };
#pragma unroll
    for (int s = 0; s < 3; s++) {
        mm_step(Abuf, Bbuf, scr, SPS, wid);
        __syncthreads();
        buildB(Bbuf, sB, scr, tid & 63, (tid >> 6) * 32, av[s], -bv[s], true);
        __syncthreads();
    }

    // ---- step 4: P = I + B + B2*r1; build A = P, B-op = P^T
    mm_step(Abuf, Bbuf, scr, SPS, wid);
    __syncthreads();
    if (tid < 64) buildA(Abuf, sB, scr, tid, 1.f, 1.f, true);
    else {
        buildB(Bbuf, sB, scr, tid - 64, 0,  1.f, -1.f, true);
        buildB(Bbuf, sB, scr, tid - 64, 32, 1.f, -1.f, true);
    }
    __syncthreads();

    // ---- squarings 1..3: X <- X*X
#pragma unroll
    for (int s = 0; s < 3; s++) {
        mm_step(Abuf, Bbuf, scr, SPS, wid);
        __syncthreads();
        if (tid < 64) buildA(Abuf, sB, scr, tid, 0.f, 0.f, true);
        else {
            buildB(Bbuf, sB, scr, tid - 64, 0,  0.f, 0.f, true);
            buildB(Bbuf, sB, scr, tid - 64, 32, 0.f, 0.f, true);
        }
        __syncthreads();
    }

    // ---- squaring 4: straight to global (row-major, ld=64)
    mm_step(Abuf, Bbuf, out + (size_t)blockIdx.x * 4096, 64, wid);
}

extern "C" void kernel_launch(void* const* d_in, const int* in_sizes, int n_in,
                              void* d_out, int out_size)
{
    const float* svec = (const float*)d_in[0];
    float* out = (float*)d_out;
    const int batch = in_sizes[0] / 2016;

    cudaFuncSetAttribute(SkewSymMatrixExp_kernel,
                         cudaFuncAttributeMaxDynamicSharedMemorySize, SMEM_BYTES);
    SkewSymMatrixExp_kernel<<<batch, 128, SMEM_BYTES>>>(svec, out);
}

// round 5
// speedup vs baseline: 2.0305x; 1.5706x over previous
#include <cuda_runtime.h>
#include <cuda_bf16.h>
#include <math.h>
#include <stdint.h>

// expm(S) for 4096 skew-symmetric 64x64 matrices.
// Scaling & squaring (s=4), degree-9 Paterson-Stockmeyer, 9 matmuls of 64^3.
// GEMMs: mma.sync.m16n8k16 bf16 split hi/lo (3 products), fp32 accumulate.
// Epilogue is fully register-resident: split + operand STS (incl. transpose)
// straight from mma accumulator fragments. No fp32 scratch buffer.

#define LDO 136     // operand pitch in bf16 elems (272 B, odd*16 -> LDSM conflict-free)
#define SBP 66      // fp32 skew-matrix pitch (even -> float2-aligned)

#define SM_A   0        // A operand: 64 rows x [hi 64 | lo 64] bf16 -> 17408 B
#define SM_B   17408    // B operand: rows n hold R^T (k hi 0-63 | lo 64-127) -> 17408 B
#define SM_SB  34816    // fp32 skew matrix, pitch 66 -> 16896 B
#define SMEM_BYTES 51712

static __device__ __forceinline__ uint32_t smem_u32(const void* p) {
    uint32_t a;
    asm("{ .reg .u64 t; cvta.to.shared.u64 t, %1; cvt.u32.u64 %0, t; }" : "=r"(a) : "l"(p));
    return a;
}
static __device__ __forceinline__ void ldsm4(uint32_t* r, uint32_t a) {
    asm volatile("ldmatrix.sync.aligned.m8n8.x4.shared.b16 {%0,%1,%2,%3}, [%4];"
        : "=r"(r[0]), "=r"(r[1]), "=r"(r[2]), "=r"(r[3]) : "r"(a));
}
static __device__ __forceinline__ void mma16816(float* c, const uint32_t* a, const uint32_t* b) {
    asm volatile("mma.sync.aligned.m16n8k16.row.col.f32.bf16.bf16.f32 "
        "{%0,%1,%2,%3}, {%4,%5,%6,%7}, {%8,%9}, {%0,%1,%2,%3};"
        : "+f"(c[0]), "+f"(c[1]), "+f"(c[2]), "+f"(c[3])
        : "r"(a[0]), "r"(a[1]), "r"(a[2]), "r"(a[3]), "r"(b[0]), "r"(b[1]));
}
static __device__ __forceinline__ void splitw(float x0, float x1, uint32_t& hw, uint32_t& lw) {
    __nv_bfloat16 h0 = __float2bfloat16(x0), h1 = __float2bfloat16(x1);
    float r0 = x0 - __bfloat162float(h0), r1 = x1 - __bfloat162float(h1);
    __nv_bfloat16 l0 = __float2bfloat16(r0), l1 = __float2bfloat16(r1);
    hw = (uint32_t)__bfloat16_as_ushort(h0) | ((uint32_t)__bfloat16_as_ushort(h1) << 16);
    lw = (uint32_t)__bfloat16_as_ushort(l0) | ((uint32_t)__bfloat16_as_ushort(l1) << 16);
}

// C(64x64) = A * R, A in Abuf rows, R^T in Bbuf rows. Warp w -> rows 16w..16w+15.
// c[nt][0..3]: (row=16w+g, col=nt*8+tg*2, +1) and (row+8, same cols).
static __device__ __forceinline__ void mm_compute(float c[8][4], uint32_t sb, int wid, int lid) {
#pragma unroll
    for (int i = 0; i < 8; i++)
#pragma unroll
        for (int j = 0; j < 4; j++) c[i][j] = 0.f;

    const int arow = 16 * wid + (lid & 15);
    const int acol = (lid >> 4) * 8;
    const uint32_t aA = sb + SM_A + (uint32_t)(arow * LDO + acol) * 2;
    const int brow = (lid & 7) + ((lid & 16) ? 8 : 0);
    const int bcol = (lid & 8) ? 8 : 0;
    const uint32_t bA = sb + SM_B + (uint32_t)(brow * LDO + bcol) * 2;

    uint32_t aH[4][4];
#pragma unroll
    for (int kt = 0; kt < 4; kt++) ldsm4(aH[kt], aA + kt * 32);

    // pass 0: Ah*Bh, pass 1: Ah*Bl, pass 2: Al*Bh
#pragma unroll
    for (int p = 0; p < 3; p++) {
        const uint32_t kboff = (p == 1) ? 128u : 0u;
#pragma unroll
        for (int kt = 0; kt < 4; kt++) {
            uint32_t aL[4];
            const uint32_t* af;
            if (p < 2) af = aH[kt];
            else { ldsm4(aL, aA + 128 + kt * 32); af = aL; }
#pragma unroll
            for (int np = 0; np < 4; np++) {
                uint32_t b4[4];
                ldsm4(b4, bA + (uint32_t)np * (16 * LDO * 2) + kboff + kt * 32);
                mma16816(c[np * 2], af, b4);
                mma16816(c[np * 2 + 1], af, b4 + 2);
            }
        }
    }
}

// Register epilogue. X[row][col] = c + (LIN ? bB*B[row][col] + aI*(row==col) : 0).
// WA: Abuf <- X rows. WB: Bbuf <- X^T. GM: write X to gout.
template <bool WA, bool WB, bool LIN, bool GM>
static __device__ __forceinline__ void epilogue(
    float c[8][4], char* smem, const float* sB, float* gout,
    int wid, int lid, float aI, float bB)
{
    __nv_bfloat16* Abuf = reinterpret_cast<__nv_bfloat16*>(smem + SM_A);
    uint16_t* Bb = reinterpret_cast<uint16_t*>(smem + SM_B);
    const int g = lid >> 2, tg = lid & 3;
    const int r0 = 16 * wid + g;
#pragma unroll
    for (int nt = 0; nt < 8; nt++) {
        const int col = nt * 8 + tg * 2;
#pragma unroll
        for (int h = 0; h < 2; h++) {
            const int row = r0 + 8 * h;
            float x0 = c[nt][2 * h], x1 = c[nt][2 * h + 1];
            if (LIN) {
                float2 bv = *reinterpret_cast<const float2*>(sB + row * SBP + col);
                x0 += bB * bv.x;
                x1 += bB * bv.y;
                if (col == row) x0 += aI;
                if (col + 1 == row) x1 += aI;
            }
            if (GM) {
                *reinterpret_cast<float2*>(gout + row * 64 + col) = make_float2(x0, x1);
            } else {
                uint32_t hw, lw;
                splitw(x0, x1, hw, lw);
                if (WA) {
                    *reinterpret_cast<uint32_t*>(Abuf + row * LDO + col) = hw;
                    *reinterpret_cast<uint32_t*>(Abuf + row * LDO + 64 + col) = lw;
                }
                if (WB) {
                    Bb[col * LDO + row] = (uint16_t)hw;
                    Bb[(col + 1) * LDO + row] = (uint16_t)(hw >> 16);
                    Bb[col * LDO + 64 + row] = (uint16_t)lw;
                    Bb[(col + 1) * LDO + 64 + row] = (uint16_t)(lw >> 16);
                }
            }
        }
    }
}

__global__ void __launch_bounds__(128, 4)
SkewSymMatrixExp_kernel(const float* __restrict__ Svec, float* __restrict__ out)
{
    extern __shared__ char smem[];
    const uint32_t sb = smem_u32(smem);
    __nv_bfloat16* Abuf = reinterpret_cast<__nv_bfloat16*>(smem + SM_A);
    uint16_t* Bb = reinterpret_cast<uint16_t*>(smem + SM_B);
    float* sB = reinterpret_cast<float*>(smem + SM_SB);

    const int tid = threadIdx.x, wid = tid >> 5, lid = tid & 31;
    const float* v = Svec + (size_t)blockIdx.x * 2016;

    // ---- scatter S_vec into fp32 skew matrix B = S/16
    if (tid < 64) sB[tid * SBP + tid] = 0.f;
    const float scl = 0.0625f;
    for (int n = tid; n < 2016; n += 128) {
        int i = (int)((127.0f - sqrtf(16129.0f - 8.0f * (float)n)) * 0.5f);
        if (i < 0) i = 0;
        if (i > 62) i = 62;
        while ((((i + 1) * (126 - i)) >> 1) <= n) ++i;
        while (((i * (127 - i)) >> 1) > n) --i;
        int j = i + 1 + (n - ((i * (127 - i)) >> 1));
        float val = v[n] * scl;
        sB[i * SBP + j] = -val;
        sB[j * SBP + i] = val;
    }
    __syncthreads();

    // ---- initial operands: Abuf <- B rows; Bbuf <- B^T rows = -B rows
    {
        const int r = tid & 63;
        const bool isA = tid < 64;
#pragma unroll 8
        for (int k = 0; k < 64; k += 2) {
            float x0 = sB[r * SBP + k], x1 = sB[r * SBP + k + 1];
            if (!isA) { x0 = -x0; x1 = -x1; }
            uint32_t hw, lw;
            splitw(x0, x1, hw, lw);
            if (isA) {
                *reinterpret_cast<uint32_t*>(Abuf + r * LDO + k) = hw;
                *reinterpret_cast<uint32_t*>(Abuf + r * LDO + 64 + k) = lw;
            } else {
                *reinterpret_cast<uint32_t*>(reinterpret_cast<__nv_bfloat16*>(Bb) + r * LDO + k) = hw;
                *reinterpret_cast<uint32_t*>(reinterpret_cast<__nv_bfloat16*>(Bb) + r * LDO + 64 + k) = lw;
            }
        }
    }
    __syncthreads();

    // Taylor coeffs a_i = 1/(2i)!, b_i = 1/(2i+1)!
    const float A4 = 2.4801587e-5f, B4 = 2.7557319e-6f;
    const float A3 = 1.3888889e-3f, B3 = 1.9841270e-4f;
    const float A2 = 4.1666668e-2f, B2c = 8.3333333e-3f;
    const float A1 = 0.5f, B1 = 1.6666667e-1f;

    float c[8][4];

    // ---- step 0: B2 = B*B. Abuf <- B2 (fixed through chain). Bbuf <- r4^T.
    mm_compute(c, sb, wid, lid);
    __syncthreads();
    epilogue<true, false, false, false>(c, smem, sB, nullptr, wid, lid, 0.f, 0.f);
    {
        // r4^T: Bbuf[n][k] = A4*(k==n) - B4*sB[n][k]
        const int n = tid >> 1;
        const int k0 = (tid & 1) * 32;
#pragma unroll 8
        for (int k = k0; k < k0 + 32; k += 2) {
            float x0 = -B4 * sB[n * SBP + k] + (k == n ? A4 : 0.f);
            float x1 = -B4 * sB[n * SBP + k + 1] + (k + 1 == n ? A4 : 0.f);
            uint32_t hw, lw;
            splitw(x0, x1, hw, lw);
            *reinterpret_cast<uint32_t*>(reinterpret_cast<__nv_bfloat16*>(Bb) + n * LDO + k) = hw;
            *reinterpret_cast<uint32_t*>(reinterpret_cast<__nv_bfloat16*>(Bb) + n * LDO + 64 + k) = lw;
        }
    }
    __syncthreads();

    // ---- chain: r_{i-1} = a I + b B + B2*r_i  (rebuild Bbuf only; Abuf stays B2)
    const float av[3] = { A3, A2, A1 };
    const float bv[3] = { B3, B2c, B1 };
#pragma unroll
    for (int s = 0; s < 3; s++) {
        mm_compute(c, sb, wid, lid);
        __syncthreads();
        epilogue<false, true, true, false>(c, smem, sB, nullptr, wid, lid, av[s], bv[s]);
        __syncthreads();
    }

    // ---- step 4: P = I + B + B2*r1. Abuf <- P, Bbuf <- P^T.
    mm_compute(c, sb, wid, lid);
    __syncthreads();
    epilogue<true, true, true, false>(c, smem, sB, nullptr, wid, lid, 1.f, 1.f);
    __syncthreads();

    // ---- squarings 1..3: X <- X*X
#pragma unroll
    for (int s = 0; s < 3; s++) {
        mm_compute(c, sb, wid, lid);
        __syncthreads();
        epilogue<true, true, false, false>(c, smem, sB, nullptr, wid, lid, 0.f, 0.f);
        __syncthreads();
    }

    // ---- squaring 4: straight to global
    mm_compute(c, sb, wid, lid);
    epilogue<false, false, false, true>(c, smem, sB, out + (size_t)blockIdx.x * 4096,
                                        wid, lid, 0.f, 0.f);
}

extern "C" void kernel_launch(void* const* d_in, const int* in_sizes, int n_in,
                              void* d_out, int out_size)
{
    const float* svec = (const float*)d_in[0];
    float* out = (float*)d_out;
    const int batch = in_sizes[0] / 2016;

    cudaFuncSetAttribute(SkewSymMatrixExp_kernel,
                         cudaFuncAttributeMaxDynamicSharedMemorySize, SMEM_BYTES);
    SkewSymMatrixExp_kernel<<<batch, 128, SMEM_BYTES>>>(svec, out);
}

// round 6
// speedup vs baseline: 2.1273x; 1.0477x over previous
#include <cuda_runtime.h>
#include <cuda_bf16.h>
#include <math.h>
#include <stdint.h>

// expm(S) for 4096 skew-symmetric 64x64 matrices.
// Scaling & squaring (s=4), degree-9 Paterson-Stockmeyer, 9 matmuls of 64^3.
// GEMMs: mma.sync.m16n8k16 bf16 split hi/lo (3 products), fp32 accumulate.
// Quadrant-per-warp mainloop loads each operand fragment exactly once per
// k-tile and issues all 3 split-products from it. Epilogue is register-
// resident; transposed operand store uses movmatrix.

#define LDO 136     // operand pitch in bf16 elems (272 B -> conflict-free LDSM)
#define SBP 66      // fp32 skew-matrix pitch

#define SM_A   0        // A operand: 64 rows x [hi 64 | lo 64] bf16 -> 17408 B
#define SM_B   17408    // B operand: row n = R^T row n, [hi|lo]    -> 17408 B
#define SM_SB  34816    // fp32 skew matrix, pitch 66 -> 16896 B
#define SMEM_BYTES 51712

static __device__ __forceinline__ uint32_t smem_u32(const void* p) {
    uint32_t a;
    asm("{ .reg .u64 t; cvta.to.shared.u64 t, %1; cvt.u32.u64 %0, t; }" : "=r"(a) : "l"(p));
    return a;
}
static __device__ __forceinline__ void ldsm4(uint32_t* r, uint32_t a) {
    asm volatile("ldmatrix.sync.aligned.m8n8.x4.shared.b16 {%0,%1,%2,%3}, [%4];"
        : "=r"(r[0]), "=r"(r[1]), "=r"(r[2]), "=r"(r[3]) : "r"(a));
}
static __device__ __forceinline__ void mma16816(float* c, const uint32_t* a, const uint32_t* b) {
    asm volatile("mma.sync.aligned.m16n8k16.row.col.f32.bf16.bf16.f32 "
        "{%0,%1,%2,%3}, {%4,%5,%6,%7}, {%8,%9}, {%0,%1,%2,%3};"
        : "+f"(c[0]), "+f"(c[1]), "+f"(c[2]), "+f"(c[3])
        : "r"(a[0]), "r"(a[1]), "r"(a[2]), "r"(a[3]), "r"(b[0]), "r"(b[1]));
}
static __device__ __forceinline__ uint32_t mov_t(uint32_t s) {
    uint32_t d;
    asm("movmatrix.sync.aligned.m8n8.trans.b16 %0, %1;" : "=r"(d) : "r"(s));
    return d;
}
static __device__ __forceinline__ void splitw(float x0, float x1, uint32_t& hw, uint32_t& lw) {
    __nv_bfloat16 h0 = __float2bfloat16(x0), h1 = __float2bfloat16(x1);
    float r0 = x0 - __bfloat162float(h0), r1 = x1 - __bfloat162float(h1);
    __nv_bfloat16 l0 = __float2bfloat16(r0), l1 = __float2bfloat16(r1);
    hw = (uint32_t)__bfloat16_as_ushort(h0) | ((uint32_t)__bfloat16_as_ushort(h1) << 16);
    lw = (uint32_t)__bfloat16_as_ushort(l0) | ((uint32_t)__bfloat16_as_ushort(l1) << 16);
}

// Warp quadrant: rows r0..r0+31 (r0 = (wid>>1)*32), cols c0..c0+31 (c0 = (wid&1)*32).
// acc c[m][j][4]: m = 16-row tile, j = 8-col tile.
static __device__ __forceinline__ void mm_compute(float c[2][4][4], uint32_t sb, int wid, int lid) {
#pragma unroll
    for (int m = 0; m < 2; m++)
#pragma unroll
        for (int j = 0; j < 4; j++)
#pragma unroll
            for (int q = 0; q < 4; q++) c[m][j][q] = 0.f;

    const int r0 = (wid >> 1) * 32, c0 = (wid & 1) * 32;
    const uint32_t aA = sb + SM_A + (uint32_t)((r0 + (lid & 15)) * LDO + (lid >> 4) * 8) * 2;
    const int brow = (lid & 7) + ((lid & 16) ? 8 : 0);
    const int bcol = (lid & 8) ? 8 : 0;
    const uint32_t bA = sb + SM_B + (uint32_t)((c0 + brow) * LDO + bcol) * 2;
    const uint32_t rstep = 16 * LDO * 2;

#pragma unroll
    for (int kt = 0; kt < 4; kt++) {
        const uint32_t ko = (uint32_t)kt * 32;
        uint32_t ah[2][4], bh[2][4];
        ldsm4(ah[0], aA + ko);
        ldsm4(ah[1], aA + rstep + ko);
        ldsm4(bh[0], bA + ko);
        ldsm4(bh[1], bA + rstep + ko);
        // Ah * Bh
#pragma unroll
        for (int m = 0; m < 2; m++)
#pragma unroll
            for (int n = 0; n < 2; n++) {
                mma16816(c[m][2 * n],     ah[m], bh[n]);
                mma16816(c[m][2 * n + 1], ah[m], bh[n] + 2);
            }
        // Ah * Bl
        {
            uint32_t bl[2][4];
            ldsm4(bl[0], bA + 128 + ko);
            ldsm4(bl[1], bA + rstep + 128 + ko);
#pragma unroll
            for (int m = 0; m < 2; m++)
#pragma unroll
                for (int n = 0; n < 2; n++) {
                    mma16816(c[m][2 * n],     ah[m], bl[n]);
                    mma16816(c[m][2 * n + 1], ah[m], bl[n] + 2);
                }
        }
        // Al * Bh
        {
            uint32_t al[2][4];
            ldsm4(al[0], aA + 128 + ko);
            ldsm4(al[1], aA + rstep + 128 + ko);
#pragma unroll
            for (int m = 0; m < 2; m++)
#pragma unroll
                for (int n = 0; n < 2; n++) {
                    mma16816(c[m][2 * n],     al[m], bh[n]);
                    mma16816(c[m][2 * n + 1], al[m], bh[n] + 2);
                }
        }
    }
}

// Register epilogue. X[row][col] = c (+ LIN: bB*B[row][col] + aI*(row==col)).
// WA: Abuf <- X rows. WB: Bbuf <- X^T (movmatrix). GM: X -> gout.
template <bool WA, bool WB, bool LIN, bool GM>
static __device__ __forceinline__ void epilogue(
    float c[2][4][4], char* smem, const float* sB, float* gout,
    int wid, int lid, float aI, float bB)
{
    __nv_bfloat16* Abuf = reinterpret_cast<__nv_bfloat16*>(smem + SM_A);
    __nv_bfloat16* Bbuf = reinterpret_cast<__nv_bfloat16*>(smem + SM_B);
    const int g = lid >> 2, tg = lid & 3;
    const int r0 = (wid >> 1) * 32, c0 = (wid & 1) * 32;
#pragma unroll
    for (int m = 0; m < 2; m++) {
#pragma unroll
        for (int j = 0; j < 4; j++) {
            const int col = c0 + 8 * j + 2 * tg;
#pragma unroll
            for (int h = 0; h < 2; h++) {
                const int row = r0 + 16 * m + 8 * h + g;
                float x0 = c[m][j][2 * h], x1 = c[m][j][2 * h + 1];
                if (LIN) {
                    float2 bv = *reinterpret_cast<const float2*>(sB + row * SBP + col);
                    x0 += bB * bv.x;
                    x1 += bB * bv.y;
                    if (col == row) x0 += aI;
                    if (col + 1 == row) x1 += aI;
                }
                if (GM) {
                    *reinterpret_cast<float2*>(gout + row * 64 + col) = make_float2(x0, x1);
                } else {
                    uint32_t hw, lw;
                    splitw(x0, x1, hw, lw);
                    if (WA) {
                        *reinterpret_cast<uint32_t*>(Abuf + row * LDO + col) = hw;
                        *reinterpret_cast<uint32_t*>(Abuf + row * LDO + 64 + col) = lw;
                    }
                    if (WB) {
                        uint32_t hwT = mov_t(hw), lwT = mov_t(lw);
                        const int trow = c0 + 8 * j + g;
                        const int tcol = r0 + 16 * m + 8 * h + 2 * tg;
                        *reinterpret_cast<uint32_t*>(Bbuf + trow * LDO + tcol) = hwT;
                        *reinterpret_cast<uint32_t*>(Bbuf + trow * LDO + 64 + tcol) = lwT;
                    }
                }
            }
        }
    }
}

__global__ void __launch_bounds__(128, 4)
SkewSymMatrixExp_kernel(const float* __restrict__ Svec, float* __restrict__ out)
{
    extern __shared__ char smem[];
    const uint32_t sb = smem_u32(smem);
    __nv_bfloat16* Abuf = reinterpret_cast<__nv_bfloat16*>(smem + SM_A);
    __nv_bfloat16* Bbuf = reinterpret_cast<__nv_bfloat16*>(smem + SM_B);
    float* sB = reinterpret_cast<float*>(smem + SM_SB);

    const int tid = threadIdx.x, wid = tid >> 5, lid = tid & 31;
    const float* v = Svec + (size_t)blockIdx.x * 2016;

    // ---- scatter S_vec into fp32 skew matrix B = S/16
    if (tid < 64) sB[tid * SBP + tid] = 0.f;
    const float scl = 0.0625f;
    for (int n = tid; n < 2016; n += 128) {
        int i = (int)((127.0f - sqrtf(16129.0f - 8.0f * (float)n)) * 0.5f);
        if (i < 0) i = 0;
        if (i > 62) i = 62;
        while ((((i + 1) * (126 - i)) >> 1) <= n) ++i;
        while (((i * (127 - i)) >> 1) > n) --i;
        int j = i + 1 + (n - ((i * (127 - i)) >> 1));
        float val = v[n] * scl;
        sB[i * SBP + j] = -val;
        sB[j * SBP + i] = val;
    }
    __syncthreads();

    // ---- initial operands: Abuf <- B rows; Bbuf <- B^T rows = -B rows
    {
        const int r = tid & 63;
        const bool isA = tid < 64;
        __nv_bfloat16* dst = isA ? Abuf : reinterpret_cast<__nv_bfloat16*>(Bbuf);
#pragma unroll 8
        for (int k = 0; k < 64; k += 2) {
            float x0 = sB[r * SBP + k], x1 = sB[r * SBP + k + 1];
            if (!isA) { x0 = -x0; x1 = -x1; }
            uint32_t hw, lw;
            splitw(x0, x1, hw, lw);
            *reinterpret_cast<uint32_t*>(dst + r * LDO + k) = hw;
            *reinterpret_cast<uint32_t*>(dst + r * LDO + 64 + k) = lw;
        }
    }
    __syncthreads();

    // Taylor coeffs a_i = 1/(2i)!, b_i = 1/(2i+1)!
    const float A4 = 2.4801587e-5f, B4 = 2.7557319e-6f;
    const float A3 = 1.3888889e-3f, B3 = 1.9841270e-4f;
    const float A2 = 4.1666668e-2f, B2c = 8.3333333e-3f;
    const float A1 = 0.5f, B1 = 1.6666667e-1f;

    float c[2][4][4];

    // ---- step 0: B2 = B*B. Abuf <- B2 (fixed through chain). Bbuf <- r4^T.
    mm_compute(c, sb, wid, lid);
    __syncthreads();
    epilogue<true, false, false, false>(c, smem, sB, nullptr, wid, lid, 0.f, 0.f);
    {
        // r4^T: Bbuf[n][k] = A4*(k==n) - B4*sB[n][k]
        const int n = tid >> 1;
        const int k0 = (tid & 1) * 32;
#pragma unroll 8
        for (int k = k0; k < k0 + 32; k += 2) {
            float x0 = -B4 * sB[n * SBP + k] + (k == n ? A4 : 0.f);
            float x1 = -B4 * sB[n * SBP + k + 1] + (k + 1 == n ? A4 : 0.f);
            uint32_t hw, lw;
            splitw(x0, x1, hw, lw);
            *reinterpret_cast<uint32_t*>(Bbuf + n * LDO + k) = hw;
            *reinterpret_cast<uint32_t*>(Bbuf + n * LDO + 64 + k) = lw;
        }
    }
    __syncthreads();

    // ---- chain: r_{i-1} = a I + b B + B2*r_i  (rebuild Bbuf only; Abuf stays B2)
    const float av[3] = { A3, A2, A1 };
    const float bv[3] = { B3, B2c, B1 };
#pragma unroll
    for (int s = 0; s < 3; s++) {
        mm_compute(c, sb, wid, lid);
        __syncthreads();
        epilogue<false, true, true, false>(c, smem, sB, nullptr, wid, lid, av[s], bv[s]);
        __syncthreads();
    }

    // ---- step 4: P = I + B + B2*r1. Abuf <- P, Bbuf <- P^T.
    mm_compute(c, sb, wid, lid);
    __syncthreads();
    epilogue<true, true, true, false>(c, smem, sB, nullptr, wid, lid, 1.f, 1.f);
    __syncthreads();

    // ---- squarings 1..3: X <- X*X
#pragma unroll
    for (int s = 0; s < 3; s++) {
        mm_compute(c, sb, wid, lid);
        __syncthreads();
        epilogue<true, true, false, false>(c, smem, sB, nullptr, wid, lid, 0.f, 0.f);
        __syncthreads();
    }

    // ---- squaring 4: straight to global
    mm_compute(c, sb, wid, lid);
    epilogue<false, false, false, true>(c, smem, sB, out + (size_t)blockIdx.x * 4096,
                                        wid, lid, 0.f, 0.f);
}

extern "C" void kernel_launch(void* const* d_in, const int* in_sizes, int n_in,
                              void* d_out, int out_size)
{
    const float* svec = (const float*)d_in[0];
    float* out = (float*)d_out;
    const int batch = in_sizes[0] / 2016;

    cudaFuncSetAttribute(SkewSymMatrixExp_kernel,
                         cudaFuncAttributeMaxDynamicSharedMemorySize, SMEM_BYTES);
    SkewSymMatrixExp_kernel<<<batch, 128, SMEM_BYTES>>>(svec, out);
}